// round 8
// baseline (speedup 1.0000x reference)
#include <cuda_runtime.h>
#include <math.h>

#define NB 32
#define CH 128
#define HW 4096           // 64*64
#define CNT 131072.0f     // NB*HW, bn population per channel
#define EPS 1e-5f

// ---------------- scratch (device globals; no mallocs allowed) ----------------
__device__ float g_s  [NB*2*HW];      // channel mean/max planes
__device__ float g_sig[NB*HW];        // spatial-attention sigmoid map
__device__ float g_x1 [NB*CH*HW];     // x * spatial att
__device__ float g_x2 [NB*CH*HW];     // x1 * channel att
__device__ float g_bufA[NB*CH*HW];    // dw outputs
__device__ float g_bufB[NB*CH*HW];    // mid pw outputs (sep)
__device__ float g_b1 [NB*CH*HW];     // maxpool branch
__device__ float g_b2 [NB*CH*HW];     // avgpool branch
__device__ float g_b4 [NB*CH*HW];     // sep3 branch (pre-bn)
__device__ float g_b5 [NB*CH*HW];     // sep5 branch
__device__ float g_b6 [NB*CH*HW];     // dil3 branch
__device__ float g_b7 [NB*CH*HW];     // dil5 branch
__device__ float g_psum[NB*CH];
__device__ float g_pmax[NB*CH];
__device__ float g_att [NB*CH];
__device__ int   g_nd[CH];
__device__ int   g_winner[CH];
__device__ float g_sum[8*CH];         // bn stats slots
__device__ float g_sq [8*CH];
__device__ float g_WT [6*CH*CH];      // transposed pw weights [ci][co]

// ---------------- tiny helper kernels ----------------
__global__ void k_zero_stats() {
    int i = blockIdx.x*256 + threadIdx.x;
    if (i < 8*CH) { g_sum[i] = 0.f; g_sq[i] = 0.f; }
}

__global__ void k_transw(const float* w0, const float* w1, const float* w2,
                         const float* w3, const float* w4, const float* w5) {
    const float* ws[6] = {w0,w1,w2,w3,w4,w5};
    const float* w = ws[blockIdx.x];
    float* o = g_WT + blockIdx.x*CH*CH;
    for (int i = threadIdx.x; i < CH*CH; i += 256) {
        int ci = i >> 7, co = i & 127;
        o[i] = w[co*CH + ci];
    }
}

// ---------------- stage A: spatial attention ----------------
// per (n,hw): mean & max over channels of original x
__global__ void k_chanstat(const float* __restrict__ x) {
    int idx = blockIdx.x*256 + threadIdx.x;       // n*HW + hw
    if (idx >= NB*HW) return;
    int n = idx >> 12, hw = idx & (HW-1);
    const float* p = x + (size_t)n*CH*HW + hw;
    float s = 0.f, m = -1e30f;
    #pragma unroll 8
    for (int c = 0; c < CH; c++) { float v = p[c*HW]; s += v; m = fmaxf(m, v); }
    g_s[n*2*HW + hw]      = s * (1.f/CH);
    g_s[n*2*HW + HW + hw] = m;
}

// 7x7 conv (2->1 ch, pad 3) + sigmoid
__global__ void k_saconv(const float* __restrict__ saw) {
    __shared__ float sp[2*HW];
    __shared__ float w[98];
    int n = blockIdx.x;
    for (int i = threadIdx.x; i < 2*HW; i += 256) sp[i] = g_s[n*2*HW + i];
    if (threadIdx.x < 98) w[threadIdx.x] = saw[threadIdx.x];
    __syncthreads();
    for (int hw = threadIdx.x; hw < HW; hw += 256) {
        int h = hw >> 6, wx = hw & 63;
        float acc = 0.f;
        #pragma unroll
        for (int ic = 0; ic < 2; ic++)
            for (int kh = 0; kh < 7; kh++) {
                int ih = h + kh - 3;
                if (ih < 0 || ih > 63) continue;
                for (int kw = 0; kw < 7; kw++) {
                    int iw = wx + kw - 3;
                    if (iw >= 0 && iw <= 63)
                        acc += sp[ic*HW + ih*64 + iw] * w[ic*49 + kh*7 + kw];
                }
            }
        g_sig[n*HW + hw] = 1.f / (1.f + __expf(-acc));
    }
}

// x1 = x * sig ; per-(n,c) sum & max over HW
__global__ void k_x1red(const float* __restrict__ x) {
    int n = blockIdx.x >> 7, c = blockIdx.x & 127;
    size_t base = ((size_t)n*CH + c)*HW;
    const float* sg = g_sig + n*HW;
    float s = 0.f, m = -1e30f;
    for (int i = threadIdx.x; i < HW; i += 256) {
        float v = x[base+i] * sg[i];
        g_x1[base+i] = v; s += v; m = fmaxf(m, v);
    }
    __shared__ float rs[256], rm[256];
    rs[threadIdx.x] = s; rm[threadIdx.x] = m; __syncthreads();
    for (int o = 128; o > 0; o >>= 1) {
        if (threadIdx.x < o) {
            rs[threadIdx.x] += rs[threadIdx.x + o];
            rm[threadIdx.x] = fmaxf(rm[threadIdx.x], rm[threadIdx.x + o]);
        }
        __syncthreads();
    }
    if (threadIdx.x == 0) { g_psum[n*CH+c] = rs[0]; g_pmax[n*CH+c] = rm[0]; }
}

// ---------------- stage B: channel attention MLP ----------------
__global__ void k_att(const float* __restrict__ fc1, const float* __restrict__ fc2) {
    int n = blockIdx.x, t = threadIdx.x;   // 128 threads
    __shared__ float m[CH], mx[CH], hm[64], hx[64];
    m[t]  = g_psum[n*CH+t] * (1.f/HW);
    mx[t] = g_pmax[n*CH+t];
    __syncthreads();
    if (t < 64) {
        float a = 0.f, b = 0.f;
        for (int c = 0; c < CH; c++) { float w = fc1[t*CH+c]; a += w*m[c]; b += w*mx[c]; }
        hm[t] = fmaxf(a, 0.f); hx[t] = fmaxf(b, 0.f);
    }
    __syncthreads();
    float a = 0.f, b = 0.f;
    for (int k = 0; k < 64; k++) { float w = fc2[t*64+k]; a += w*hm[k]; b += w*hx[k]; }
    g_att[n*CH+t] = 1.f / (1.f + __expf(-(a + b)));
}

// slist sum, top-k ranks, num_dict, winner (last-wins scatter)
__global__ void k_topk(const int* __restrict__ perm) {
    int c = threadIdx.x;   // 128 threads
    __shared__ float sl[CH];
    float s = 0.f;
    for (int n = 0; n < NB; n++) s += g_att[n*CH + c];
    sl[c] = s; __syncthreads();
    float v = sl[c];
    int rank = 0;
    for (int d = 0; d < CH; d++) { float u = sl[d]; rank += (u > v) || (u == v && d < c); }
    if (rank < 96) g_nd[rank] = c;
    if (c < 32) g_nd[96 + c] = perm[c];
    int win;
    if (c < 32) {
        int inv = 0;
        for (int i = 0; i < 32; i++) if (perm[i] == c) inv = i;
        win = 96 + inv;                 // perm positions are last -> always win
    } else {
        win = (rank < 96) ? rank : -1;
    }
    g_winner[c] = win;
}

__global__ void k_x2() {
    int b = blockIdx.x;     // n*CH + c
    float a = g_att[b];
    size_t base = (size_t)b * HW;
    for (int i = threadIdx.x; i < HW; i += 256)
        g_x2[base+i] = g_x1[base+i] * a;
}

// ---------------- stage C: branches ----------------
// fused max & avg 3x3 pool on xt (= x2 gathered by nd), with bn stats slots 0/1
__global__ void k_pool() {
    __shared__ float pl[HW];
    int n = blockIdx.x >> 7, j = blockIdx.x & 127;
    int cin = g_nd[j];
    size_t ib = ((size_t)n*CH + cin)*HW, ob = ((size_t)n*CH + j)*HW;
    for (int i = threadIdx.x; i < HW; i += 256) pl[i] = g_x2[ib+i];
    __syncthreads();
    float s1 = 0.f, q1 = 0.f, s2 = 0.f, q2 = 0.f;
    for (int i = threadIdx.x; i < HW; i += 256) {
        int h = i >> 6, w = i & 63;
        int h0 = max(h-1,0), h1 = min(h+1,63), w0 = max(w-1,0), w1 = min(w+1,63);
        float mx = -1e30f, sm = 0.f;
        for (int hh = h0; hh <= h1; hh++)
            for (int ww = w0; ww <= w1; ww++) {
                float v = pl[hh*64+ww];
                mx = fmaxf(mx, v); sm += v;
            }
        float av = sm / (float)((h1-h0+1)*(w1-w0+1));
        g_b1[ob+i] = mx; g_b2[ob+i] = av;
        s1 += mx; q1 += mx*mx; s2 += av; q2 += av*av;
    }
    __syncthreads();
    pl[threadIdx.x] = s1; pl[256+threadIdx.x] = q1;
    pl[512+threadIdx.x] = s2; pl[768+threadIdx.x] = q2;
    __syncthreads();
    for (int o = 128; o > 0; o >>= 1) {
        if (threadIdx.x < o) {
            pl[threadIdx.x]     += pl[threadIdx.x+o];
            pl[256+threadIdx.x] += pl[256+threadIdx.x+o];
            pl[512+threadIdx.x] += pl[512+threadIdx.x+o];
            pl[768+threadIdx.x] += pl[768+threadIdx.x+o];
        }
        __syncthreads();
    }
    if (threadIdx.x == 0) {
        atomicAdd(&g_sum[0*CH+j], pl[0]);   atomicAdd(&g_sq[0*CH+j], pl[256]);
        atomicAdd(&g_sum[1*CH+j], pl[512]); atomicAdd(&g_sq[1*CH+j], pl[768]);
    }
}

// depthwise conv; pre-op: slot<0 -> relu(in), slot>=0 -> relu(bn_slot(in))
// nd != null -> gather input channel through nd (first-stage dw reading x2)
template<int KS, int DIL>
__global__ void k_dw(const float* __restrict__ in, const float* __restrict__ dwW,
                     float* __restrict__ out, const int* __restrict__ nd, int slot) {
    __shared__ float pl[HW];
    __shared__ float wt[KS*KS];
    __shared__ float bnp[2];
    int n = blockIdx.x >> 7, j = blockIdx.x & 127;
    int cin = nd ? nd[j] : j;
    if (threadIdx.x == 0) {
        if (slot >= 0) {
            float mean = g_sum[slot*CH + j] / CNT;
            float var  = g_sq [slot*CH + j] / CNT - mean*mean;
            bnp[0] = mean; bnp[1] = rsqrtf(var + EPS);
        } else { bnp[0] = 0.f; bnp[1] = 1.f; }
    }
    if (threadIdx.x < KS*KS) wt[threadIdx.x] = dwW[j*KS*KS + threadIdx.x];
    __syncthreads();
    float mean = bnp[0], rstd = bnp[1];
    size_t ib = ((size_t)n*CH + cin)*HW;
    for (int i = threadIdx.x; i < HW; i += 256) {
        float v = (in[ib+i] - mean) * rstd;
        pl[i] = fmaxf(v, 0.f);
    }
    __syncthreads();
    size_t ob = ((size_t)n*CH + j)*HW;
    constexpr int R = DIL * (KS/2);
    for (int i = threadIdx.x; i < HW; i += 256) {
        int h = i >> 6, w = i & 63;
        float acc = 0.f;
        #pragma unroll
        for (int kh = 0; kh < KS; kh++) {
            int ih = h - R + kh*DIL;
            if (ih < 0 || ih > 63) continue;
            #pragma unroll
            for (int kw = 0; kw < KS; kw++) {
                int iw = w - R + kw*DIL;
                if (iw >= 0 && iw <= 63)
                    acc += pl[ih*64 + iw] * wt[kh*KS + kw];
            }
        }
        out[ob+i] = acc;
    }
}

// pointwise 1x1 conv = GEMM: out[co,p] = sum_ci WT[ci][co] * in[ci,p]
// tile 128co x 64p per block, 4x8 microtile/thread. bn stats into slot.
__global__ void __launch_bounds__(256) k_pw(const float* __restrict__ in,
                                            const float* __restrict__ wt,
                                            float* __restrict__ out, int slot) {
    extern __shared__ float smem[];
    float* sW = smem;           // 128*128
    float* sI = smem + CH*CH;   // 128*64
    int n = blockIdx.x >> 6;
    int pbase = (blockIdx.x & 63) * 64;
    for (int i = threadIdx.x; i < CH*CH; i += 256) sW[i] = wt[i];
    for (int i = threadIdx.x; i < CH*64; i += 256) {
        int ci = i >> 6, p = i & 63;
        sI[i] = in[((size_t)n*CH + ci)*HW + pbase + p];
    }
    __syncthreads();
    int ty = threadIdx.x >> 3, tx = threadIdx.x & 7;
    int co0 = ty*4, p0 = tx*8;
    float acc[4][8];
    #pragma unroll
    for (int i = 0; i < 4; i++)
        #pragma unroll
        for (int k = 0; k < 8; k++) acc[i][k] = 0.f;
    #pragma unroll 4
    for (int ci = 0; ci < CH; ci++) {
        float wv[4], av[8];
        *(float4*)&wv[0] = *(const float4*)&sW[ci*CH + co0];
        *(float4*)&av[0] = *(const float4*)&sI[ci*64 + p0];
        *(float4*)&av[4] = *(const float4*)&sI[ci*64 + p0 + 4];
        #pragma unroll
        for (int i = 0; i < 4; i++)
            #pragma unroll
            for (int k = 0; k < 8; k++) acc[i][k] += wv[i]*av[k];
    }
    #pragma unroll
    for (int i = 0; i < 4; i++) {
        int co = co0 + i;
        float* op = &out[((size_t)n*CH + co)*HW + pbase + p0];
        *(float4*)&op[0] = *(float4*)&acc[i][0];
        *(float4*)&op[4] = *(float4*)&acc[i][4];
        float s = 0.f, q = 0.f;
        #pragma unroll
        for (int k = 0; k < 8; k++) { s += acc[i][k]; q += acc[i][k]*acc[i][k]; }
        // reduce across the 8-lane tx group (lanes are 8-aligned within warp)
        for (int o = 4; o > 0; o >>= 1) {
            s += __shfl_down_sync(0xffffffffu, s, o, 8);
            q += __shfl_down_sync(0xffffffffu, q, o, 8);
        }
        if (tx == 0) {
            atomicAdd(&g_sum[slot*CH + co], s);
            atomicAdd(&g_sq [slot*CH + co], q);
        }
    }
}

// ---------------- final: weighted branch sum (+bn) and scatter ----------------
__global__ void k_final(const float* __restrict__ wts, float* __restrict__ out) {
    int n = blockIdx.x >> 7, c = blockIdx.x & 127;
    int win = g_winner[c];
    size_t ob = ((size_t)n*CH + c)*HW;
    if (win < 0) {
        for (int i = threadIdx.x; i < HW; i += 256) out[ob+i] = g_x2[ob+i];
        return;
    }
    int j = win;
    __shared__ float P[12];
    __shared__ float W[8];
    if (threadIdx.x < 8) W[threadIdx.x] = wts[threadIdx.x];
    if (threadIdx.x == 0) {
        const int slots[6] = {0,1,3,5,6,7};
        for (int q = 0; q < 6; q++) {
            float mean = g_sum[slots[q]*CH + j] / CNT;
            float var  = g_sq [slots[q]*CH + j] / CNT - mean*mean;
            P[q*2] = mean; P[q*2+1] = rsqrtf(var + EPS);
        }
    }
    __syncthreads();
    size_t jb = ((size_t)n*CH + j)*HW;
    for (int i = threadIdx.x; i < HW; i += 256) {
        float r = W[3]*g_x2[ob+i];
        r += W[1]*((g_b1[jb+i]-P[0]) *P[1]);
        r += W[2]*((g_b2[jb+i]-P[2]) *P[3]);
        r += W[4]*((g_b4[jb+i]-P[4]) *P[5]);
        r += W[5]*((g_b5[jb+i]-P[6]) *P[7]);
        r += W[6]*((g_b6[jb+i]-P[8]) *P[9]);
        r += W[7]*((g_b7[jb+i]-P[10])*P[11]);
        out[ob+i] = r;
    }
}

// ---------------- launch ----------------
extern "C" void kernel_launch(void* const* d_in, const int* in_sizes, int n_in,
                              void* d_out, int out_size) {
    const float* x    = (const float*)d_in[0];
    const float* wts  = (const float*)d_in[1];
    const float* fc1  = (const float*)d_in[2];
    const float* fc2  = (const float*)d_in[3];
    const float* saw  = (const float*)d_in[4];
    const float* s3d1 = (const float*)d_in[5];
    const float* s3p1 = (const float*)d_in[6];
    const float* s3d2 = (const float*)d_in[7];
    const float* s3p2 = (const float*)d_in[8];
    const float* s5d1 = (const float*)d_in[9];
    const float* s5p1 = (const float*)d_in[10];
    const float* s5d2 = (const float*)d_in[11];
    const float* s5p2 = (const float*)d_in[12];
    const float* d3d  = (const float*)d_in[13];
    const float* d3p  = (const float*)d_in[14];
    const float* d5d  = (const float*)d_in[15];
    const float* d5p  = (const float*)d_in[16];
    const int*   perm = (const int*)d_in[17];
    float* out = (float*)d_out;

    // CRITICAL: resolve real device addresses of __device__ globals.
    // (Passing the symbols directly from host code passes the host shadow
    //  address, which GB300's ATS happily dereferences -> silent garbage.)
    float *p_x2, *p_bufA, *p_bufB, *p_b4, *p_b5, *p_b6, *p_b7, *p_WT;
    int   *p_nd;
    cudaGetSymbolAddress((void**)&p_x2,  g_x2);
    cudaGetSymbolAddress((void**)&p_bufA, g_bufA);
    cudaGetSymbolAddress((void**)&p_bufB, g_bufB);
    cudaGetSymbolAddress((void**)&p_b4,  g_b4);
    cudaGetSymbolAddress((void**)&p_b5,  g_b5);
    cudaGetSymbolAddress((void**)&p_b6,  g_b6);
    cudaGetSymbolAddress((void**)&p_b7,  g_b7);
    cudaGetSymbolAddress((void**)&p_WT,  g_WT);
    cudaGetSymbolAddress((void**)&p_nd,  g_nd);

    const int PW_SMEM = (CH*CH + CH*64) * (int)sizeof(float); // 96 KB
    cudaFuncSetAttribute(k_pw, cudaFuncAttributeMaxDynamicSharedMemorySize, PW_SMEM);

    k_zero_stats<<<4, 256>>>();
    k_transw<<<6, 256>>>(s3p1, s3p2, s5p1, s5p2, d3p, d5p);

    k_chanstat<<<(NB*HW)/256, 256>>>(x);
    k_saconv<<<NB, 256>>>(saw);
    k_x1red<<<NB*CH, 256>>>(x);
    k_att<<<NB, 128>>>(fc1, fc2);
    k_topk<<<1, 128>>>(perm);
    k_x2<<<NB*CH, 256>>>();

    k_pool<<<NB*CH, 256>>>();

    // sep3: relu -> dw3 -> pw1(stats s2) -> bn+relu -> dw3 -> pw2(stats s3)
    k_dw<3,1><<<NB*CH, 256>>>(p_x2,  s3d1, p_bufA, p_nd, -1);
    k_pw<<<NB*64, 256, PW_SMEM>>>(p_bufA, p_WT + 0*CH*CH, p_bufB, 2);
    k_dw<3,1><<<NB*CH, 256>>>(p_bufB, s3d2, p_bufA, (const int*)nullptr, 2);
    k_pw<<<NB*64, 256, PW_SMEM>>>(p_bufA, p_WT + 1*CH*CH, p_b4, 3);

    // sep5
    k_dw<5,1><<<NB*CH, 256>>>(p_x2,  s5d1, p_bufA, p_nd, -1);
    k_pw<<<NB*64, 256, PW_SMEM>>>(p_bufA, p_WT + 2*CH*CH, p_bufB, 4);
    k_dw<5,1><<<NB*CH, 256>>>(p_bufB, s5d2, p_bufA, (const int*)nullptr, 4);
    k_pw<<<NB*64, 256, PW_SMEM>>>(p_bufA, p_WT + 3*CH*CH, p_b5, 5);

    // dil3 (3x3 dil2 pad2)
    k_dw<3,2><<<NB*CH, 256>>>(p_x2, d3d, p_bufA, p_nd, -1);
    k_pw<<<NB*64, 256, PW_SMEM>>>(p_bufA, p_WT + 4*CH*CH, p_b6, 6);

    // dil5 (5x5 dil2 pad4)
    k_dw<5,2><<<NB*CH, 256>>>(p_x2, d5d, p_bufA, p_nd, -1);
    k_pw<<<NB*64, 256, PW_SMEM>>>(p_bufA, p_WT + 5*CH*CH, p_b7, 7);

    k_final<<<NB*CH, 256>>>(wts, out);
}